// round 2
// baseline (speedup 1.0000x reference)
#include <cuda_runtime.h>
#include <cuda_bf16.h>

#define NPTS 32768
#define EDG  786432
#define KMAX 64
#define CIN  16
#define CMID 64
#define COUT 64

// Scratch: product matrix [N][CIN*CMID] (c-major: index c*64+m), 128 MB.
__device__ float g_prod[NPTS * CIN * CMID];
__device__ int   g_start[NPTS];
__device__ int   g_end[NPTS];

__global__ void init_bounds_kernel() {
    int i = blockIdx.x * blockDim.x + threadIdx.x;
    if (i < NPTS) { g_start[i] = 0; g_end[i] = 0; }
}

// out_index is sorted ascending: mark segment boundaries.
__global__ void seg_bounds_kernel(const int* __restrict__ out_index) {
    int e = blockIdx.x * blockDim.x + threadIdx.x;
    if (e >= EDG) return;
    int v = out_index[e];
    if (e == 0) {
        g_start[v] = 0;
    } else {
        int pv = out_index[e - 1];
        if (pv != v) { g_start[v] = e; g_end[pv] = e; }
    }
    if (e == EDG - 1) g_end[v] = EDG;
}

__device__ __forceinline__ float celu1(float x) {
    return x > 0.f ? x : (__expf(x) - 1.f);
}

// One block (64 threads) per output point.
// Stage 1: threads (j = tid/16, c = tid%16) over a tile of 4 edges:
//   h[j][c] = celu(pos_local . W1[:,c]),  sx[j][c] = x_in[i][c] / count
// Stage 2: threads (m = tid) : M = celu(h . W2[:,m]); acc[c] += sx[c]*M
__global__ __launch_bounds__(64) void edge_kernel(
    const float* __restrict__ x_in,
    const float* __restrict__ pos_in,
    const float* __restrict__ pos_out,
    const int*   __restrict__ in_index,
    const float* __restrict__ W1,
    const float* __restrict__ W2)
{
    __shared__ float sW1[48];
    __shared__ float sW2[CIN * CMID];
    __shared__ float sh[4][CIN];
    __shared__ float sx[4][CIN];

    const int tid = threadIdx.x;
    const int n   = blockIdx.x;

    if (tid < 48) sW1[tid] = W1[tid];
    #pragma unroll
    for (int i = tid; i < CIN * CMID; i += 64) sW2[i] = W2[i];

    const int s   = g_start[n];
    const int e   = g_end[n];
    const int cnt = e - s;
    const float inv = (cnt > 0) ? (1.f / (float)cnt) : 0.f;
    const int use = (cnt < KMAX) ? cnt : KMAX;   // JAX scatter drops slot >= K

    const float pox = pos_out[3 * n + 0];
    const float poy = pos_out[3 * n + 1];
    const float poz = pos_out[3 * n + 2];

    float acc[CIN];
    #pragma unroll
    for (int c = 0; c < CIN; c++) acc[c] = 0.f;

    const int j = tid >> 4;
    const int c = tid & 15;

    __syncthreads();

    for (int base = 0; base < use; base += 4) {
        // ---- stage 1: gather + first layer ----
        int eidx = base + j;
        float hv = 0.f, xv = 0.f;
        if (eidx < use) {
            int i = in_index[s + eidx];
            float p0 = pos_in[3 * i + 0] - pox;
            float p1 = pos_in[3 * i + 1] - poy;
            float p2 = pos_in[3 * i + 2] - poz;
            hv = celu1(p0 * sW1[c] + p1 * sW1[16 + c] + p2 * sW1[32 + c]);
            xv = x_in[i * CIN + c] * inv;
        }
        sh[j][c] = hv;
        sx[j][c] = xv;
        __syncthreads();

        // ---- stage 2: second layer + outer-product accumulate ----
        const int m = tid;
        #pragma unroll
        for (int jj = 0; jj < 4; jj++) {
            float d = 0.f;
            #pragma unroll
            for (int cc = 0; cc < CIN; cc++)
                d += sh[jj][cc] * sW2[cc * CMID + m];
            float Mv = celu1(d);
            #pragma unroll
            for (int cc = 0; cc < CIN; cc++)
                acc[cc] += sx[jj][cc] * Mv;
        }
        __syncthreads();
    }

    float* gp = g_prod + (size_t)n * (CIN * CMID);
    #pragma unroll
    for (int cc = 0; cc < CIN; cc++)
        gp[cc * CMID + tid] = acc[cc];
}

// out[n][o] = sum_q prod[n][q] * W3[q][o] + b3[o]
// Block: 64 rows x 64 cols, 256 threads, 4x4 register tile per thread.
__global__ __launch_bounds__(256) void out_gemm_kernel(
    const float* __restrict__ W3,
    const float* __restrict__ b3,
    float* __restrict__ out)
{
    __shared__ float sA[64][68];   // [row][kk], padded
    __shared__ float sB[64][68];   // [kk][o],  padded (68 % 4 == 0 for float4)

    const int tid = threadIdx.x;
    const int tc  = tid & 15;      // col group  (o = tc*4 .. tc*4+3)
    const int tr  = tid >> 4;      // row group  (r = tr*4 .. tr*4+3)
    const int n0  = blockIdx.x * 64;

    float acc[4][4];
    #pragma unroll
    for (int i = 0; i < 4; i++)
        #pragma unroll
        for (int jj = 0; jj < 4; jj++) acc[i][jj] = 0.f;

    for (int kt = 0; kt < 16; kt++) {
        const int k0 = kt * 64;
        // load A tile: 64 rows x 64 k (16 elems per thread, coalesced)
        #pragma unroll
        for (int it = 0; it < 16; it++) {
            int lin = tid + it * 256;
            int rr = lin >> 6, kk = lin & 63;
            sA[rr][kk] = g_prod[(size_t)(n0 + rr) * 1024 + k0 + kk];
        }
        // load B tile: 64 k x 64 o (fully contiguous in W3)
        #pragma unroll
        for (int it = 0; it < 16; it++) {
            int lin = tid + it * 256;
            int kk = lin >> 6, oo = lin & 63;
            sB[kk][oo] = W3[(size_t)(k0 + kk) * 64 + oo];
        }
        __syncthreads();

        #pragma unroll
        for (int kk = 0; kk < 64; kk++) {
            float4 w = *(const float4*)&sB[kk][tc * 4];
            #pragma unroll
            for (int ii = 0; ii < 4; ii++) {
                float a = sA[tr * 4 + ii][kk];
                acc[ii][0] += a * w.x;
                acc[ii][1] += a * w.y;
                acc[ii][2] += a * w.z;
                acc[ii][3] += a * w.w;
            }
        }
        __syncthreads();
    }

    #pragma unroll
    for (int ii = 0; ii < 4; ii++) {
        int row = n0 + tr * 4 + ii;
        float4 r;
        r.x = acc[ii][0] + b3[tc * 4 + 0];
        r.y = acc[ii][1] + b3[tc * 4 + 1];
        r.z = acc[ii][2] + b3[tc * 4 + 2];
        r.w = acc[ii][3] + b3[tc * 4 + 3];
        *(float4*)&out[(size_t)row * 64 + tc * 4] = r;
    }
}

extern "C" void kernel_launch(void* const* d_in, const int* in_sizes, int n_in,
                              void* d_out, int out_size) {
    const float* x_in      = (const float*)d_in[0];
    const float* pos_in    = (const float*)d_in[1];
    const float* pos_out   = (const float*)d_in[2];
    const int*   in_index  = (const int*)d_in[3];
    const int*   out_index = (const int*)d_in[4];
    const float* W1        = (const float*)d_in[5];
    const float* W2        = (const float*)d_in[6];
    const float* W3        = (const float*)d_in[7];
    const float* b3        = (const float*)d_in[8];
    float* out = (float*)d_out;

    init_bounds_kernel<<<NPTS / 256, 256>>>();
    seg_bounds_kernel<<<EDG / 256, 256>>>(out_index);
    edge_kernel<<<NPTS, 64>>>(x_in, pos_in, pos_out, in_index, W1, W2);
    out_gemm_kernel<<<NPTS / 64, 256>>>(W3, b3, out);
}